// round 16
// baseline (speedup 1.0000x reference)
#include <cuda_runtime.h>

#define Bc 8
#define Sc 1024
#define DMc 512
#define Hc 8
#define Dc 64

// ---------------- device scratch ----------------
__device__ float g_Q[Bc*Hc*Sc*Dc];          // [bh][s][d]
__device__ float g_K[Bc*Hc*Sc*Dc];          // [bh][s][d]
__device__ float g_V[Bc*Hc*Sc*Dc];          // [bh][s][d]
__device__ float g_Vt[Bc*Hc*Dc*Sc];         // [bh][d][s]
__device__ float g_ctx[Bc*Sc*DMc];          // [b*s][512]
__device__ float g_Wt[4*DMc*DMc];           // [which][n][k]
__device__ float g_scores[Bc*Hc*Sc*Sc];     // [bh][q][k] masked scores s
__device__ float g_edgeM[Bc*Sc*Sc];         // mask? -1e9 : edge

__device__ __forceinline__ unsigned f2tf(float x) {
    unsigned u;
    asm("cvt.rna.tf32.f32 %0, %1;" : "=r"(u) : "f"(x));
    return u;
}

__device__ __forceinline__ void mma8(float* c, const unsigned* a, const unsigned* b) {
    asm volatile(
        "mma.sync.aligned.m16n8k8.row.col.f32.tf32.tf32.f32 "
        "{%0,%1,%2,%3}, {%4,%5,%6,%7}, {%8,%9}, {%0,%1,%2,%3};"
        : "+f"(c[0]), "+f"(c[1]), "+f"(c[2]), "+f"(c[3])
        : "r"(a[0]), "r"(a[1]), "r"(a[2]), "r"(a[3]), "r"(b[0]), "r"(b[1]));
}

__device__ __forceinline__ float2 ldcs2(const float* p) {
    float2 v;
    asm volatile("ld.global.cs.v2.f32 {%0,%1}, [%2];" : "=f"(v.x), "=f"(v.y) : "l"(p));
    return v;
}
__device__ __forceinline__ float4 ldcs4(const float* p) {
    float4 v;
    asm volatile("ld.global.cs.v4.f32 {%0,%1,%2,%3}, [%4];"
                 : "=f"(v.x), "=f"(v.y), "=f"(v.z), "=f"(v.w) : "l"(p));
    return v;
}
__device__ __forceinline__ void stcs2(float* p, float2 v) {
    asm volatile("st.global.cs.v2.f32 [%0], {%1,%2};" :: "l"(p), "f"(v.x), "f"(v.y) : "memory");
}
__device__ __forceinline__ void stcs4(float* p, float4 v) {
    asm volatile("st.global.cs.v4.f32 [%0], {%1,%2,%3,%4};"
                 :: "l"(p), "f"(v.x), "f"(v.y), "f"(v.z), "f"(v.w) : "memory");
}

// ---------------- transpose W: g_Wt[i][n][k] = W_i[k][n] ----------------
__global__ void transpose_w(const float* __restrict__ W0, const float* __restrict__ W1,
                            const float* __restrict__ W2, const float* __restrict__ W3)
{
    __shared__ float t[32][33];
    const float* W = (blockIdx.z == 0) ? W0 : (blockIdx.z == 1) ? W1 : (blockIdx.z == 2) ? W2 : W3;
    float* out = g_Wt + blockIdx.z * DMc * DMc;
    int x0 = blockIdx.x * 32, y0 = blockIdx.y * 32;
    int tx = threadIdx.x, ty = threadIdx.y;
#pragma unroll
    for (int j = 0; j < 32; j += 8) t[ty + j][tx] = W[(y0 + ty + j) * DMc + x0 + tx];
    __syncthreads();
#pragma unroll
    for (int j = 0; j < 32; j += 8) out[(x0 + ty + j) * DMc + y0 + tx] = t[tx][ty + j];
}

// ---------------- proj_plus: z<3 QKV GEMMs; z==3 edgeM prepass ---------------
__global__ __launch_bounds__(256) void proj_plus(const float* __restrict__ A0,
                                                 const float* __restrict__ A1,
                                                 const float* __restrict__ A2,
                                                 const int* __restrict__ mask,
                                                 const float* __restrict__ edge)
{
    extern __shared__ unsigned dyn[];
    int sel = blockIdx.z;
    int tid = threadIdx.x;

    if (sel == 3) {
        int base = (blockIdx.y * 4 + blockIdx.x) * 8192 + tid;
#pragma unroll 8
        for (int k = 0; k < 32; k++) {
            int i = base + k * 256;
            int4 m = ((const int4*)mask)[i];
            float4 e = ((const float4*)edge)[i];
            float4 o;
            o.x = m.x ? -1e9f : e.x;
            o.y = m.y ? -1e9f : e.y;
            o.z = m.z ? -1e9f : e.z;
            o.w = m.w ? -1e9f : e.w;
            stcs4(&g_edgeM[4 * (size_t)i], o);
        }
        return;
    }

    const float* Ap = (sel == 0) ? A0 : (sel == 1) ? A1 : A2;
    const float* Wt = g_Wt + sel * DMc * DMc;

    int w = tid >> 5, lane = tid & 31, gid = lane >> 2, qid = lane & 3;
    int warp_m = (w >> 2) * 64, warp_n = (w & 3) * 32;
    int m0 = blockIdx.y * 128, n0 = blockIdx.x * 128;

    float2 ra[8], rb[8];
    float acc[4][4][4];
#pragma unroll
    for (int i = 0; i < 4; i++)
#pragma unroll
        for (int j = 0; j < 4; j++)
#pragma unroll
            for (int r = 0; r < 4; r++) acc[i][j][r] = 0.f;

#pragma unroll
    for (int u = 0; u < 8; u++) {
        int e = tid + 256 * u;
        int m = e >> 4, k2 = e & 15;
        ra[u] = *(const float2*)&Ap[(m0 + m) * 512 + 2 * k2];
        rb[u] = *(const float2*)&Wt[(n0 + m) * 512 + 2 * k2];
    }
#pragma unroll
    for (int u = 0; u < 8; u++) {
        int e = tid + 256 * u;
        int m = e >> 4, k2 = e & 15;
        *(uint2*)&dyn[m * 36 + 2 * k2] = make_uint2(f2tf(ra[u].x), f2tf(ra[u].y));
        *(uint2*)&dyn[128 * 36 + m * 36 + 2 * k2] = make_uint2(f2tf(rb[u].x), f2tf(rb[u].y));
    }
    __syncthreads();

    int buf = 0;
    for (int kt = 0; kt < 512; kt += 32) {
        bool more = (kt + 32) < 512;
        if (more) {
#pragma unroll
            for (int u = 0; u < 8; u++) {
                int e = tid + 256 * u;
                int m = e >> 4, k2 = e & 15;
                ra[u] = *(const float2*)&Ap[(m0 + m) * 512 + kt + 32 + 2 * k2];
                rb[u] = *(const float2*)&Wt[(n0 + m) * 512 + kt + 32 + 2 * k2];
            }
        }
        {
            unsigned* Asb = dyn + buf * 2 * 128 * 36;
            unsigned* Bsb = Asb + 128 * 36;
#pragma unroll
            for (int ks = 0; ks < 4; ks++) {
                unsigned a[4][4], b[4][2];
#pragma unroll
                for (int mf = 0; mf < 4; mf++) {
                    int r = warp_m + mf * 16 + gid;
                    a[mf][0] = Asb[r * 36 + ks * 8 + qid];
                    a[mf][1] = Asb[(r + 8) * 36 + ks * 8 + qid];
                    a[mf][2] = Asb[r * 36 + ks * 8 + qid + 4];
                    a[mf][3] = Asb[(r + 8) * 36 + ks * 8 + qid + 4];
                }
#pragma unroll
                for (int nf = 0; nf < 4; nf++) {
                    int r = warp_n + nf * 8 + gid;
                    b[nf][0] = Bsb[r * 36 + ks * 8 + qid];
                    b[nf][1] = Bsb[r * 36 + ks * 8 + qid + 4];
                }
#pragma unroll
                for (int mf = 0; mf < 4; mf++)
#pragma unroll
                    for (int nf = 0; nf < 4; nf++)
                        mma8(acc[mf][nf], a[mf], b[nf]);
            }
        }
        if (more) {
            unsigned* Asb = dyn + (buf ^ 1) * 2 * 128 * 36;
            unsigned* Bsb = Asb + 128 * 36;
#pragma unroll
            for (int u = 0; u < 8; u++) {
                int e = tid + 256 * u;
                int m = e >> 4, k2 = e & 15;
                *(uint2*)&Asb[m * 36 + 2 * k2] = make_uint2(f2tf(ra[u].x), f2tf(ra[u].y));
                *(uint2*)&Bsb[m * 36 + 2 * k2] = make_uint2(f2tf(rb[u].x), f2tf(rb[u].y));
            }
        }
        __syncthreads();
        buf ^= 1;
    }

    float* dst = (sel == 0) ? g_Q : (sel == 1) ? g_K : g_V;
#pragma unroll
    for (int mf = 0; mf < 4; mf++)
#pragma unroll
        for (int nf = 0; nf < 4; nf++) {
            int m = m0 + warp_m + mf * 16 + gid;
            int n = n0 + warp_n + nf * 8 + qid * 2;
            int b_ = m >> 10, s = m & 1023;
            int h = n >> 6, d = n & 63;
            *(float2*)&dst[((b_ * Hc + h) * Sc + s) * Dc + d] =
                make_float2(acc[mf][nf][0], acc[mf][nf][1]);
            *(float2*)&dst[((b_ * Hc + h) * Sc + s + 8) * Dc + d] =
                make_float2(acc[mf][nf][2], acc[mf][nf][3]);
        }
}

// ---------------- scores_plus: z<64 scores tiles; z>=64 transpose_v ----------
__global__ __launch_bounds__(256) void scores_plus()
{
    extern __shared__ unsigned sm_u[];
    int tid = threadIdx.x;

    if (blockIdx.z >= 64) {
        float (*t)[33] = (float(*)[33])sm_u;
        int bh = blockIdx.z - 64;
        int tt = blockIdx.y * 8 + blockIdx.x;
        int s0 = (tt >> 1) * 32, d0 = (tt & 1) * 32;
        const float* V = g_V + (size_t)bh * Sc * Dc;
        float* Vt = g_Vt + (size_t)bh * Dc * Sc;
        int tx = tid & 31, ty = tid >> 5;
#pragma unroll
        for (int j = 0; j < 32; j += 8) t[ty + j][tx] = V[(s0 + ty + j) * Dc + d0 + tx];
        __syncthreads();
#pragma unroll
        for (int j = 0; j < 32; j += 8) Vt[(d0 + ty + j) * Sc + s0 + tx] = t[tx][ty + j];
        return;
    }

    unsigned (*Qs)[68] = (unsigned(*)[68])sm_u;
    unsigned (*Ks)[68] = (unsigned(*)[68])(sm_u + 128 * 68);

    int w = tid >> 5, lane = tid & 31, gid = lane >> 2, qid = lane & 3;
    int warp_m = (w >> 2) * 64, warp_n = (w & 3) * 32;
    int k0 = blockIdx.x * 128, q0 = blockIdx.y * 128;
    int bh = blockIdx.z;
    int b = bh >> 3;

    const float* Qg = g_Q + ((size_t)bh * Sc + q0) * Dc;
    const float* Kg = g_K + ((size_t)bh * Sc + k0) * Dc;
#pragma unroll
    for (int u = 0; u < 16; u++) {
        int e = tid + 256 * u;
        int r = e >> 5, k2 = e & 31;
        float2 qv = *(const float2*)&Qg[r * 64 + 2 * k2];
        float2 kv = *(const float2*)&Kg[r * 64 + 2 * k2];
        *(uint2*)&Qs[r][2 * k2] = make_uint2(f2tf(qv.x), f2tf(qv.y));
        *(uint2*)&Ks[r][2 * k2] = make_uint2(f2tf(kv.x), f2tf(kv.y));
    }
    __syncthreads();

    float acc[4][4][4];
#pragma unroll
    for (int i = 0; i < 4; i++)
#pragma unroll
        for (int j = 0; j < 4; j++)
#pragma unroll
            for (int r = 0; r < 4; r++) acc[i][j][r] = 0.f;

#pragma unroll
    for (int ks = 0; ks < 8; ks++) {
        unsigned a[4][4], bb[4][2];
#pragma unroll
        for (int mf = 0; mf < 4; mf++) {
            int r = warp_m + mf * 16 + gid;
            a[mf][0] = Qs[r][ks * 8 + qid];
            a[mf][1] = Qs[r + 8][ks * 8 + qid];
            a[mf][2] = Qs[r][ks * 8 + qid + 4];
            a[mf][3] = Qs[r + 8][ks * 8 + qid + 4];
        }
#pragma unroll
        for (int nf = 0; nf < 4; nf++) {
            int r = warp_n + nf * 8 + gid;
            bb[nf][0] = Ks[r][ks * 8 + qid];
            bb[nf][1] = Ks[r][ks * 8 + qid + 4];
        }
#pragma unroll
        for (int mf = 0; mf < 4; mf++)
#pragma unroll
            for (int nf = 0; nf < 4; nf++)
                mma8(acc[mf][nf], a[mf], bb[nf]);
    }

#pragma unroll
    for (int mf = 0; mf < 4; mf++)
#pragma unroll
        for (int nf = 0; nf < 4; nf++) {
            int q = q0 + warp_m + mf * 16 + gid;
            int kc = k0 + warp_n + nf * 8 + qid * 2;
#pragma unroll
            for (int half = 0; half < 2; half++) {
                int qq = q + half * 8;
                size_t rowe = (size_t)(b * Sc + qq) * Sc;
                float2 ev = ldcs2(&g_edgeM[rowe + kc]);
                float c0 = acc[mf][nf][half * 2 + 0] * 0.125f + ev.x;
                float c1 = acc[mf][nf][half * 2 + 1] * 0.125f + ev.y;
                stcs2(&g_scores[((size_t)bh * Sc + qq) * Sc + kc], make_float2(c0, c1));
            }
        }
}

// ---------------- AV (R12 shape: float2 staging, stride 36, natural regs) ----
// grid (8 qtiles, 64 bh), block 256; block tile 128q x 64d, K chunks of 32.
__global__ __launch_bounds__(256) void av_mma()
{
    extern __shared__ unsigned dynv[];
    // layout: [buf][P(128x36) | V(64x36)]
    __shared__ float sl[128];

    int tid = threadIdx.x;
    int w = tid >> 5, lane = tid & 31, gid = lane >> 2, qid = lane & 3;
    int warp_m = (w >> 1) * 32, warp_n = (w & 1) * 32;
    int q0 = blockIdx.x * 128;
    int bh = blockIdx.y;
    int b = bh >> 3, h = bh & 7;

    float2 rp[8], rv[4];
    float lacc[8];
#pragma unroll
    for (int u = 0; u < 8; u++) lacc[u] = 0.f;

    float acc[2][4][4];
#pragma unroll
    for (int i = 0; i < 2; i++)
#pragma unroll
        for (int j = 0; j < 4; j++)
#pragma unroll
            for (int r = 0; r < 4; r++) acc[i][j][r] = 0.f;

    // prologue kt = 0
#pragma unroll
    for (int u = 0; u < 8; u++) {
        int e = tid + 256 * u;
        int q = e >> 4, k2 = e & 15;
        rp[u] = ldcs2(&g_scores[((size_t)bh * Sc + q0 + q) * Sc + 2 * k2]);
    }
#pragma unroll
    for (int u = 0; u < 4; u++) {
        int e = tid + 256 * u;
        int d = e >> 4, k2 = e & 15;
        rv[u] = *(const float2*)&g_Vt[((size_t)bh * Dc + d) * Sc + 2 * k2];
    }
    {
        unsigned* Pb = dynv;
        unsigned* Vb = dynv + 128 * 36;
#pragma unroll
        for (int u = 0; u < 8; u++) {
            int e = tid + 256 * u;
            int q = e >> 4, k2 = e & 15;
            float px = __expf(rp[u].x), py = __expf(rp[u].y);
            lacc[u] += px + py;
            *(uint2*)&Pb[q * 36 + 2 * k2] = make_uint2(f2tf(px), f2tf(py));
        }
#pragma unroll
        for (int u = 0; u < 4; u++) {
            int e = tid + 256 * u;
            int d = e >> 4, k2 = e & 15;
            *(uint2*)&Vb[d * 36 + 2 * k2] = make_uint2(f2tf(rv[u].x), f2tf(rv[u].y));
        }
    }
    __syncthreads();

    int buf = 0;
    for (int kt = 0; kt < 1024; kt += 32) {
        bool more = (kt + 32) < 1024;
        if (more) {
#pragma unroll
            for (int u = 0; u < 8; u++) {
                int e = tid + 256 * u;
                int q = e >> 4, k2 = e & 15;
                rp[u] = ldcs2(&g_scores[((size_t)bh * Sc + q0 + q) * Sc + kt + 32 + 2 * k2]);
            }
#pragma unroll
            for (int u = 0; u < 4; u++) {
                int e = tid + 256 * u;
                int d = e >> 4, k2 = e & 15;
                rv[u] = *(const float2*)&g_Vt[((size_t)bh * Dc + d) * Sc + kt + 32 + 2 * k2];
            }
        }
        {
            unsigned* Pb = dynv + buf * (128 + 64) * 36;
            unsigned* Vb = Pb + 128 * 36;
#pragma unroll
            for (int ks = 0; ks < 4; ks++) {
                unsigned a[2][4], bb[4][2];
#pragma unroll
                for (int mf = 0; mf < 2; mf++) {
                    int r = warp_m + mf * 16 + gid;
                    a[mf][0] = Pb[r * 36 + ks * 8 + qid];
                    a[mf][1] = Pb[(r + 8) * 36 + ks * 8 + qid];
                    a[mf][2] = Pb[r * 36 + ks * 8 + qid + 4];
                    a[mf][3] = Pb[(r + 8) * 36 + ks * 8 + qid + 4];
                }
#pragma unroll
                for (int nf = 0; nf < 4; nf++) {
                    int r = warp_n + nf * 8 + gid;
                    bb[nf][0] = Vb[r * 36 + ks * 8 + qid];
                    bb[nf][1] = Vb[r * 36 + ks * 8 + qid + 4];
                }
#pragma unroll
                for (int mf = 0; mf < 2; mf++)
#pragma unroll
                    for (int nf = 0; nf < 4; nf++)
                        mma8(acc[mf][nf], a[mf], bb[nf]);
            }
        }
        if (more) {
            unsigned* Pb = dynv + (buf ^ 1) * (128 + 64) * 36;
            unsigned* Vb = Pb + 128 * 36;
#pragma unroll
            for (int u = 0; u < 8; u++) {
                int e = tid + 256 * u;
                int q = e >> 4, k2 = e & 15;
                float px = __expf(rp[u].x), py = __expf(rp[u].y);
                lacc[u] += px + py;
                *(uint2*)&Pb[q * 36 + 2 * k2] = make_uint2(f2tf(px), f2tf(py));
            }
#pragma unroll
            for (int u = 0; u < 4; u++) {
                int e = tid + 256 * u;
                int d = e >> 4, k2 = e & 15;
                *(uint2*)&Vb[d * 36 + 2 * k2] = make_uint2(f2tf(rv[u].x), f2tf(rv[u].y));
            }
        }
        __syncthreads();
        buf ^= 1;
    }

    // reduce lacc across the 16 lanes (k-dim) sharing each staged row
#pragma unroll
    for (int u = 0; u < 8; u++) {
        float v = lacc[u];
        v += __shfl_xor_sync(0xffffffffu, v, 1);
        v += __shfl_xor_sync(0xffffffffu, v, 2);
        v += __shfl_xor_sync(0xffffffffu, v, 4);
        v += __shfl_xor_sync(0xffffffffu, v, 8);
        if ((lane & 15) == 0) sl[16 * u + (tid >> 4)] = v;
    }
    __syncthreads();

#pragma unroll
    for (int mf = 0; mf < 2; mf++)
#pragma unroll
        for (int nf = 0; nf < 4; nf++) {
            int ql = warp_m + mf * 16 + gid;
            float li0 = 1.f / sl[ql];
            float li1 = 1.f / sl[ql + 8];
            int q = q0 + ql;
            int dcol = warp_n + nf * 8 + qid * 2;
            *(float2*)&g_ctx[((size_t)(b * Sc) + q) * DMc + h * Dc + dcol] =
                make_float2(acc[mf][nf][0] * li0, acc[mf][nf][1] * li0);
            *(float2*)&g_ctx[((size_t)(b * Sc) + q + 8) * DMc + h * Dc + dcol] =
                make_float2(acc[mf][nf][2] * li1, acc[mf][nf][3] * li1);
        }
}

// ---------------- fc_plus: z==0 fc GEMM; z>=1 avg_reduce ---------------------
__global__ __launch_bounds__(256) void fc_plus(float* __restrict__ Cplain,
                                               float* __restrict__ out_avg)
{
    extern __shared__ unsigned dyn[];
    int tid = threadIdx.x;

    if (blockIdx.z >= 1) {
        int bq = (blockIdx.z - 1) * 256 + blockIdx.y * 4 + blockIdx.x;
        int b = bq >> 10, q = bq & 1023;
        int k = tid * 4;
        float4 av = make_float4(0.f, 0.f, 0.f, 0.f);
#pragma unroll
        for (int h = 0; h < 8; h++) {
            const float* row = g_scores + ((size_t)(b * 8 + h) * Sc + q) * Sc;
            float4 v = ldcs4(&row[k]);
            av.x += v.x; av.y += v.y; av.z += v.z; av.w += v.w;
        }
        av.x *= 0.125f; av.y *= 0.125f; av.z *= 0.125f; av.w *= 0.125f;
        stcs4(&out_avg[(size_t)bq * Sc + k], av);
        return;
    }

    const float* Ap = g_ctx;
    const float* Wt = g_Wt + 3 * DMc * DMc;

    int w = tid >> 5, lane = tid & 31, gid = lane >> 2, qid = lane & 3;
    int warp_m = (w >> 2) * 64, warp_n = (w & 3) * 32;
    int m0 = blockIdx.y * 128, n0 = blockIdx.x * 128;

    float2 ra[8], rb[8];
    float acc[4][4][4];
#pragma unroll
    for (int i = 0; i < 4; i++)
#pragma unroll
        for (int j = 0; j < 4; j++)
#pragma unroll
            for (int r = 0; r < 4; r++) acc[i][j][r] = 0.f;

#pragma unroll
    for (int u = 0; u < 8; u++) {
        int e = tid + 256 * u;
        int m = e >> 4, k2 = e & 15;
        ra[u] = *(const float2*)&Ap[(m0 + m) * 512 + 2 * k2];
        rb[u] = *(const float2*)&Wt[(n0 + m) * 512 + 2 * k2];
    }
#pragma unroll
    for (int u = 0; u < 8; u++) {
        int e = tid + 256 * u;
        int m = e >> 4, k2 = e & 15;
        *(uint2*)&dyn[m * 36 + 2 * k2] = make_uint2(f2tf(ra[u].x), f2tf(ra[u].y));
        *(uint2*)&dyn[128 * 36 + m * 36 + 2 * k2] = make_uint2(f2tf(rb[u].x), f2tf(rb[u].y));
    }
    __syncthreads();

    int buf = 0;
    for (int kt = 0; kt < 512; kt += 32) {
        bool more = (kt + 32) < 512;
        if (more) {
#pragma unroll
            for (int u = 0; u < 8; u++) {
                int e = tid + 256 * u;
                int m = e >> 4, k2 = e & 15;
                ra[u] = *(const float2*)&Ap[(m0 + m) * 512 + kt + 32 + 2 * k2];
                rb[u] = *(const float2*)&Wt[(n0 + m) * 512 + kt + 32 + 2 * k2];
            }
        }
        {
            unsigned* Asb = dyn + buf * 2 * 128 * 36;
            unsigned* Bsb = Asb + 128 * 36;
#pragma unroll
            for (int ks = 0; ks < 4; ks++) {
                unsigned a[4][4], b[4][2];
#pragma unroll
                for (int mf = 0; mf < 4; mf++) {
                    int r = warp_m + mf * 16 + gid;
                    a[mf][0] = Asb[r * 36 + ks * 8 + qid];
                    a[mf][1] = Asb[(r + 8) * 36 + ks * 8 + qid];
                    a[mf][2] = Asb[r * 36 + ks * 8 + qid + 4];
                    a[mf][3] = Asb[(r + 8) * 36 + ks * 8 + qid + 4];
                }
#pragma unroll
                for (int nf = 0; nf < 4; nf++) {
                    int r = warp_n + nf * 8 + gid;
                    b[nf][0] = Bsb[r * 36 + ks * 8 + qid];
                    b[nf][1] = Bsb[r * 36 + ks * 8 + qid + 4];
                }
#pragma unroll
                for (int mf = 0; mf < 4; mf++)
#pragma unroll
                    for (int nf = 0; nf < 4; nf++)
                        mma8(acc[mf][nf], a[mf], b[nf]);
            }
        }
        if (more) {
            unsigned* Asb = dyn + (buf ^ 1) * 2 * 128 * 36;
            unsigned* Bsb = Asb + 128 * 36;
#pragma unroll
            for (int u = 0; u < 8; u++) {
                int e = tid + 256 * u;
                int m = e >> 4, k2 = e & 15;
                *(uint2*)&Asb[m * 36 + 2 * k2] = make_uint2(f2tf(ra[u].x), f2tf(ra[u].y));
                *(uint2*)&Bsb[m * 36 + 2 * k2] = make_uint2(f2tf(rb[u].x), f2tf(rb[u].y));
            }
        }
        __syncthreads();
        buf ^= 1;
    }

#pragma unroll
    for (int mf = 0; mf < 4; mf++)
#pragma unroll
        for (int nf = 0; nf < 4; nf++) {
            int m = m0 + warp_m + mf * 16 + gid;
            int n = n0 + warp_n + nf * 8 + qid * 2;
            *(float2*)&Cplain[m * 512 + n] = make_float2(acc[mf][nf][0], acc[mf][nf][1]);
            *(float2*)&Cplain[(m + 8) * 512 + n] = make_float2(acc[mf][nf][2], acc[mf][nf][3]);
        }
}

// ---------------- launch ------------------------------------------------------
extern "C" void kernel_launch(void* const* d_in, const int* in_sizes, int n_in,
                              void* d_out, int out_size)
{
    (void)in_sizes; (void)n_in; (void)out_size;
    const float* inQ  = (const float*)d_in[0];
    const float* inK  = (const float*)d_in[1];
    const float* inV  = (const float*)d_in[2];
    const int*   mask = (const int*)d_in[3];
    const float* edge = (const float*)d_in[4];
    const float* WQ   = (const float*)d_in[5];
    const float* WK   = (const float*)d_in[6];
    const float* WV   = (const float*)d_in[7];
    const float* Wfc  = (const float*)d_in[8];

    float* out     = (float*)d_out;
    float* out_avg = out + Bc * Sc * DMc;

    const int GEMM_SMEM = 2 * 2 * 128 * 36 * 4;      // 73728
    const int SC_SMEM   = 2 * 128 * 68 * 4;          // 69632
    const int AV_SMEM   = 2 * (128 + 64) * 36 * 4;   // 55296
    cudaFuncSetAttribute(proj_plus,   cudaFuncAttributeMaxDynamicSharedMemorySize, GEMM_SMEM);
    cudaFuncSetAttribute(fc_plus,     cudaFuncAttributeMaxDynamicSharedMemorySize, GEMM_SMEM);
    cudaFuncSetAttribute(scores_plus, cudaFuncAttributeMaxDynamicSharedMemorySize, SC_SMEM);
    cudaFuncSetAttribute(av_mma,      cudaFuncAttributeMaxDynamicSharedMemorySize, AV_SMEM);

    transpose_w<<<dim3(16, 16, 4), dim3(32, 8)>>>(WQ, WK, WV, Wfc);

    proj_plus<<<dim3(4, 64, 4), 256, GEMM_SMEM>>>(inQ, inK, inV, mask, edge);

    scores_plus<<<dim3(8, 8, 128), 256, SC_SMEM>>>();

    av_mma<<<dim3(8, 64), 256, AV_SMEM>>>();

    fc_plus<<<dim3(4, 64, 33), 256, GEMM_SMEM>>>(out, out_avg);
}

// round 17
// speedup vs baseline: 1.1881x; 1.1881x over previous
#include <cuda_runtime.h>

#define Bc 8
#define Sc 1024
#define DMc 512
#define Hc 8
#define Dc 64

// ---------------- device scratch ----------------
__device__ float g_Q[Bc*Hc*Sc*Dc];          // [bh][s][d]
__device__ float g_K[Bc*Hc*Sc*Dc];          // [bh][s][d]
__device__ float g_V[Bc*Hc*Sc*Dc];          // [bh][s][d]
__device__ float g_Vt[Bc*Hc*Dc*Sc];         // [bh][d][s]
__device__ float g_ctx[Bc*Sc*DMc];          // [b*s][512]
__device__ float g_Wt[4*DMc*DMc];           // [which][n][k]
__device__ float g_scores[Bc*Hc*Sc*Sc];     // [bh][q][k] masked scores s
__device__ float g_edgeM[Bc*Sc*Sc];         // mask? -1e9 : edge

__device__ __forceinline__ unsigned f2tf(float x) {
    unsigned u;
    asm("cvt.rna.tf32.f32 %0, %1;" : "=r"(u) : "f"(x));
    return u;
}

__device__ __forceinline__ void mma8(float* c, const unsigned* a, const unsigned* b) {
    asm volatile(
        "mma.sync.aligned.m16n8k8.row.col.f32.tf32.tf32.f32 "
        "{%0,%1,%2,%3}, {%4,%5,%6,%7}, {%8,%9}, {%0,%1,%2,%3};"
        : "+f"(c[0]), "+f"(c[1]), "+f"(c[2]), "+f"(c[3])
        : "r"(a[0]), "r"(a[1]), "r"(a[2]), "r"(a[3]), "r"(b[0]), "r"(b[1]));
}

// ---------------- transpose W: g_Wt[i][n][k] = W_i[k][n] ----------------
__global__ void transpose_w(const float* __restrict__ W0, const float* __restrict__ W1,
                            const float* __restrict__ W2, const float* __restrict__ W3)
{
    __shared__ float t[32][33];
    const float* W = (blockIdx.z == 0) ? W0 : (blockIdx.z == 1) ? W1 : (blockIdx.z == 2) ? W2 : W3;
    float* out = g_Wt + blockIdx.z * DMc * DMc;
    int x0 = blockIdx.x * 32, y0 = blockIdx.y * 32;
    int tx = threadIdx.x, ty = threadIdx.y;
#pragma unroll
    for (int j = 0; j < 32; j += 8) t[ty + j][tx] = W[(y0 + ty + j) * DMc + x0 + tx];
    __syncthreads();
#pragma unroll
    for (int j = 0; j < 32; j += 8) out[(x0 + ty + j) * DMc + y0 + tx] = t[tx][ty + j];
}

// ---------------- proj_plus: z<3 QKV GEMMs; z==3 edgeM prepass ---------------
__global__ __launch_bounds__(256) void proj_plus(const float* __restrict__ A0,
                                                 const float* __restrict__ A1,
                                                 const float* __restrict__ A2,
                                                 const int* __restrict__ mask,
                                                 const float* __restrict__ edge)
{
    extern __shared__ unsigned dyn[];
    int sel = blockIdx.z;
    int tid = threadIdx.x;

    if (sel == 3) {
        int base = (blockIdx.y * 4 + blockIdx.x) * 8192 + tid;
#pragma unroll 8
        for (int k = 0; k < 32; k++) {
            int i = base + k * 256;
            int4 m = ((const int4*)mask)[i];
            float4 e = ((const float4*)edge)[i];
            float4 o;
            o.x = m.x ? -1e9f : e.x;
            o.y = m.y ? -1e9f : e.y;
            o.z = m.z ? -1e9f : e.z;
            o.w = m.w ? -1e9f : e.w;
            ((float4*)g_edgeM)[i] = o;
        }
        return;
    }

    const float* Ap = (sel == 0) ? A0 : (sel == 1) ? A1 : A2;
    const float* Wt = g_Wt + sel * DMc * DMc;

    int w = tid >> 5, lane = tid & 31, gid = lane >> 2, qid = lane & 3;
    int warp_m = (w >> 2) * 64, warp_n = (w & 3) * 32;
    int m0 = blockIdx.y * 128, n0 = blockIdx.x * 128;

    float2 ra[8], rb[8];
    float acc[4][4][4];
#pragma unroll
    for (int i = 0; i < 4; i++)
#pragma unroll
        for (int j = 0; j < 4; j++)
#pragma unroll
            for (int r = 0; r < 4; r++) acc[i][j][r] = 0.f;

#pragma unroll
    for (int u = 0; u < 8; u++) {
        int e = tid + 256 * u;
        int m = e >> 4, k2 = e & 15;
        ra[u] = *(const float2*)&Ap[(m0 + m) * 512 + 2 * k2];
        rb[u] = *(const float2*)&Wt[(n0 + m) * 512 + 2 * k2];
    }
#pragma unroll
    for (int u = 0; u < 8; u++) {
        int e = tid + 256 * u;
        int m = e >> 4, k2 = e & 15;
        *(uint2*)&dyn[m * 36 + 2 * k2] = make_uint2(f2tf(ra[u].x), f2tf(ra[u].y));
        *(uint2*)&dyn[128 * 36 + m * 36 + 2 * k2] = make_uint2(f2tf(rb[u].x), f2tf(rb[u].y));
    }
    __syncthreads();

    int buf = 0;
    for (int kt = 0; kt < 512; kt += 32) {
        bool more = (kt + 32) < 512;
        if (more) {
#pragma unroll
            for (int u = 0; u < 8; u++) {
                int e = tid + 256 * u;
                int m = e >> 4, k2 = e & 15;
                ra[u] = *(const float2*)&Ap[(m0 + m) * 512 + kt + 32 + 2 * k2];
                rb[u] = *(const float2*)&Wt[(n0 + m) * 512 + kt + 32 + 2 * k2];
            }
        }
        {
            unsigned* Asb = dyn + buf * 2 * 128 * 36;
            unsigned* Bsb = Asb + 128 * 36;
#pragma unroll
            for (int ks = 0; ks < 4; ks++) {
                unsigned a[4][4], b[4][2];
#pragma unroll
                for (int mf = 0; mf < 4; mf++) {
                    int r = warp_m + mf * 16 + gid;
                    a[mf][0] = Asb[r * 36 + ks * 8 + qid];
                    a[mf][1] = Asb[(r + 8) * 36 + ks * 8 + qid];
                    a[mf][2] = Asb[r * 36 + ks * 8 + qid + 4];
                    a[mf][3] = Asb[(r + 8) * 36 + ks * 8 + qid + 4];
                }
#pragma unroll
                for (int nf = 0; nf < 4; nf++) {
                    int r = warp_n + nf * 8 + gid;
                    b[nf][0] = Bsb[r * 36 + ks * 8 + qid];
                    b[nf][1] = Bsb[r * 36 + ks * 8 + qid + 4];
                }
#pragma unroll
                for (int mf = 0; mf < 4; mf++)
#pragma unroll
                    for (int nf = 0; nf < 4; nf++)
                        mma8(acc[mf][nf], a[mf], b[nf]);
            }
        }
        if (more) {
            unsigned* Asb = dyn + (buf ^ 1) * 2 * 128 * 36;
            unsigned* Bsb = Asb + 128 * 36;
#pragma unroll
            for (int u = 0; u < 8; u++) {
                int e = tid + 256 * u;
                int m = e >> 4, k2 = e & 15;
                *(uint2*)&Asb[m * 36 + 2 * k2] = make_uint2(f2tf(ra[u].x), f2tf(ra[u].y));
                *(uint2*)&Bsb[m * 36 + 2 * k2] = make_uint2(f2tf(rb[u].x), f2tf(rb[u].y));
            }
        }
        __syncthreads();
        buf ^= 1;
    }

    float* dst = (sel == 0) ? g_Q : (sel == 1) ? g_K : g_V;
#pragma unroll
    for (int mf = 0; mf < 4; mf++)
#pragma unroll
        for (int nf = 0; nf < 4; nf++) {
            int m = m0 + warp_m + mf * 16 + gid;
            int n = n0 + warp_n + nf * 8 + qid * 2;
            int b_ = m >> 10, s = m & 1023;
            int h = n >> 6, d = n & 63;
            *(float2*)&dst[((b_ * Hc + h) * Sc + s) * Dc + d] =
                make_float2(acc[mf][nf][0], acc[mf][nf][1]);
            *(float2*)&dst[((b_ * Hc + h) * Sc + s + 8) * Dc + d] =
                make_float2(acc[mf][nf][2], acc[mf][nf][3]);
        }
}

// ---------------- scores_plus: z<64 scores tiles; z>=64 transpose_v ----------
__global__ __launch_bounds__(256) void scores_plus()
{
    extern __shared__ unsigned sm_u[];
    int tid = threadIdx.x;

    if (blockIdx.z >= 64) {
        float (*t)[33] = (float(*)[33])sm_u;
        int bh = blockIdx.z - 64;
        int tt = blockIdx.y * 8 + blockIdx.x;
        int s0 = (tt >> 1) * 32, d0 = (tt & 1) * 32;
        const float* V = g_V + (size_t)bh * Sc * Dc;
        float* Vt = g_Vt + (size_t)bh * Dc * Sc;
        int tx = tid & 31, ty = tid >> 5;
#pragma unroll
        for (int j = 0; j < 32; j += 8) t[ty + j][tx] = V[(s0 + ty + j) * Dc + d0 + tx];
        __syncthreads();
#pragma unroll
        for (int j = 0; j < 32; j += 8) Vt[(d0 + ty + j) * Sc + s0 + tx] = t[tx][ty + j];
        return;
    }

    unsigned (*Qs)[68] = (unsigned(*)[68])sm_u;
    unsigned (*Ks)[68] = (unsigned(*)[68])(sm_u + 128 * 68);

    int w = tid >> 5, lane = tid & 31, gid = lane >> 2, qid = lane & 3;
    int warp_m = (w >> 2) * 64, warp_n = (w & 3) * 32;
    int k0 = blockIdx.x * 128, q0 = blockIdx.y * 128;
    int bh = blockIdx.z;
    int b = bh >> 3;

    const float* Qg = g_Q + ((size_t)bh * Sc + q0) * Dc;
    const float* Kg = g_K + ((size_t)bh * Sc + k0) * Dc;
#pragma unroll
    for (int u = 0; u < 16; u++) {
        int e = tid + 256 * u;
        int r = e >> 5, k2 = e & 31;
        float2 qv = *(const float2*)&Qg[r * 64 + 2 * k2];
        float2 kv = *(const float2*)&Kg[r * 64 + 2 * k2];
        *(uint2*)&Qs[r][2 * k2] = make_uint2(f2tf(qv.x), f2tf(qv.y));
        *(uint2*)&Ks[r][2 * k2] = make_uint2(f2tf(kv.x), f2tf(kv.y));
    }
    __syncthreads();

    float acc[4][4][4];
#pragma unroll
    for (int i = 0; i < 4; i++)
#pragma unroll
        for (int j = 0; j < 4; j++)
#pragma unroll
            for (int r = 0; r < 4; r++) acc[i][j][r] = 0.f;

#pragma unroll
    for (int ks = 0; ks < 8; ks++) {
        unsigned a[4][4], bb[4][2];
#pragma unroll
        for (int mf = 0; mf < 4; mf++) {
            int r = warp_m + mf * 16 + gid;
            a[mf][0] = Qs[r][ks * 8 + qid];
            a[mf][1] = Qs[r + 8][ks * 8 + qid];
            a[mf][2] = Qs[r][ks * 8 + qid + 4];
            a[mf][3] = Qs[r + 8][ks * 8 + qid + 4];
        }
#pragma unroll
        for (int nf = 0; nf < 4; nf++) {
            int r = warp_n + nf * 8 + gid;
            bb[nf][0] = Ks[r][ks * 8 + qid];
            bb[nf][1] = Ks[r][ks * 8 + qid + 4];
        }
#pragma unroll
        for (int mf = 0; mf < 4; mf++)
#pragma unroll
            for (int nf = 0; nf < 4; nf++)
                mma8(acc[mf][nf], a[mf], bb[nf]);
    }

#pragma unroll
    for (int mf = 0; mf < 4; mf++)
#pragma unroll
        for (int nf = 0; nf < 4; nf++) {
            int q = q0 + warp_m + mf * 16 + gid;
            int kc = k0 + warp_n + nf * 8 + qid * 2;
#pragma unroll
            for (int half = 0; half < 2; half++) {
                int qq = q + half * 8;
                size_t rowe = (size_t)(b * Sc + qq) * Sc;
                float2 ev = *(const float2*)&g_edgeM[rowe + kc];
                float c0 = acc[mf][nf][half * 2 + 0] * 0.125f + ev.x;
                float c1 = acc[mf][nf][half * 2 + 1] * 0.125f + ev.y;
                *(float2*)&g_scores[((size_t)bh * Sc + qq) * Sc + kc] =
                    make_float2(c0, c1);
            }
        }
}

// ---------------- av_plus: z==0 AV MMA; z>=1 avg_reduce ----------------------
// AV: grid (8 qtiles, 64 bh, z=0), block 256; tile 128q x 64d, K chunks of 32.
// avg: z=1..16, bq = (z-1)*512 + y*8 + x; both read g_scores concurrently so
// the second reader hits L2 behind the first.
__global__ __launch_bounds__(256) void av_plus(float* __restrict__ out_avg)
{
    extern __shared__ unsigned dynv[];
    // layout: [buf][P(128x36) | V(64x36)]
    __shared__ float sl[128];

    int tid = threadIdx.x;

    if (blockIdx.z >= 1) {
        int bq = (blockIdx.z - 1) * 512 + blockIdx.y * 8 + blockIdx.x;
        int b = bq >> 10, q = bq & 1023;
        int k = tid * 4;
        float4 av = make_float4(0.f, 0.f, 0.f, 0.f);
#pragma unroll
        for (int h = 0; h < 8; h++) {
            const float* row = g_scores + ((size_t)(b * 8 + h) * Sc + q) * Sc;
            float4 v = *(const float4*)&row[k];
            av.x += v.x; av.y += v.y; av.z += v.z; av.w += v.w;
        }
        av.x *= 0.125f; av.y *= 0.125f; av.z *= 0.125f; av.w *= 0.125f;
        *(float4*)&out_avg[(size_t)bq * Sc + k] = av;
        return;
    }

    int w = tid >> 5, lane = tid & 31, gid = lane >> 2, qid = lane & 3;
    int warp_m = (w >> 1) * 32, warp_n = (w & 1) * 32;
    int q0 = blockIdx.x * 128;
    int bh = blockIdx.y;
    int b = bh >> 3, h = bh & 7;

    float2 rp[8], rv[4];
    float lacc[8];
#pragma unroll
    for (int u = 0; u < 8; u++) lacc[u] = 0.f;

    float acc[2][4][4];
#pragma unroll
    for (int i = 0; i < 2; i++)
#pragma unroll
        for (int j = 0; j < 4; j++)
#pragma unroll
            for (int r = 0; r < 4; r++) acc[i][j][r] = 0.f;

    // prologue kt = 0
#pragma unroll
    for (int u = 0; u < 8; u++) {
        int e = tid + 256 * u;
        int q = e >> 4, k2 = e & 15;
        rp[u] = *(const float2*)&g_scores[((size_t)bh * Sc + q0 + q) * Sc + 2 * k2];
    }
#pragma unroll
    for (int u = 0; u < 4; u++) {
        int e = tid + 256 * u;
        int d = e >> 4, k2 = e & 15;
        rv[u] = *(const float2*)&g_Vt[((size_t)bh * Dc + d) * Sc + 2 * k2];
    }
    {
        unsigned* Pb = dynv;
        unsigned* Vb = dynv + 128 * 36;
#pragma unroll
        for (int u = 0; u < 8; u++) {
            int e = tid + 256 * u;
            int q = e >> 4, k2 = e & 15;
            float px = __expf(rp[u].x), py = __expf(rp[u].y);
            lacc[u] += px + py;
            *(uint2*)&Pb[q * 36 + 2 * k2] = make_uint2(f2tf(px), f2tf(py));
        }
#pragma unroll
        for (int u = 0; u < 4; u++) {
            int e = tid + 256 * u;
            int d = e >> 4, k2 = e & 15;
            *(uint2*)&Vb[d * 36 + 2 * k2] = make_uint2(f2tf(rv[u].x), f2tf(rv[u].y));
        }
    }
    __syncthreads();

    int buf = 0;
    for (int kt = 0; kt < 1024; kt += 32) {
        bool more = (kt + 32) < 1024;
        if (more) {
#pragma unroll
            for (int u = 0; u < 8; u++) {
                int e = tid + 256 * u;
                int q = e >> 4, k2 = e & 15;
                rp[u] = *(const float2*)&g_scores[((size_t)bh * Sc + q0 + q) * Sc + kt + 32 + 2 * k2];
            }
#pragma unroll
            for (int u = 0; u < 4; u++) {
                int e = tid + 256 * u;
                int d = e >> 4, k2 = e & 15;
                rv[u] = *(const float2*)&g_Vt[((size_t)bh * Dc + d) * Sc + kt + 32 + 2 * k2];
            }
        }
        {
            unsigned* Pb = dynv + buf * (128 + 64) * 36;
            unsigned* Vb = Pb + 128 * 36;
#pragma unroll
            for (int ks = 0; ks < 4; ks++) {
                unsigned a[2][4], bb[4][2];
#pragma unroll
                for (int mf = 0; mf < 2; mf++) {
                    int r = warp_m + mf * 16 + gid;
                    a[mf][0] = Pb[r * 36 + ks * 8 + qid];
                    a[mf][1] = Pb[(r + 8) * 36 + ks * 8 + qid];
                    a[mf][2] = Pb[r * 36 + ks * 8 + qid + 4];
                    a[mf][3] = Pb[(r + 8) * 36 + ks * 8 + qid + 4];
                }
#pragma unroll
                for (int nf = 0; nf < 4; nf++) {
                    int r = warp_n + nf * 8 + gid;
                    bb[nf][0] = Vb[r * 36 + ks * 8 + qid];
                    bb[nf][1] = Vb[r * 36 + ks * 8 + qid + 4];
                }
#pragma unroll
                for (int mf = 0; mf < 2; mf++)
#pragma unroll
                    for (int nf = 0; nf < 4; nf++)
                        mma8(acc[mf][nf], a[mf], bb[nf]);
            }
        }
        if (more) {
            unsigned* Pb = dynv + (buf ^ 1) * (128 + 64) * 36;
            unsigned* Vb = Pb + 128 * 36;
#pragma unroll
            for (int u = 0; u < 8; u++) {
                int e = tid + 256 * u;
                int q = e >> 4, k2 = e & 15;
                float px = __expf(rp[u].x), py = __expf(rp[u].y);
                lacc[u] += px + py;
                *(uint2*)&Pb[q * 36 + 2 * k2] = make_uint2(f2tf(px), f2tf(py));
            }
#pragma unroll
            for (int u = 0; u < 4; u++) {
                int e = tid + 256 * u;
                int d = e >> 4, k2 = e & 15;
                *(uint2*)&Vb[d * 36 + 2 * k2] = make_uint2(f2tf(rv[u].x), f2tf(rv[u].y));
            }
        }
        __syncthreads();
        buf ^= 1;
    }

    // reduce lacc across the 16 lanes (k-dim) sharing each staged row
#pragma unroll
    for (int u = 0; u < 8; u++) {
        float v = lacc[u];
        v += __shfl_xor_sync(0xffffffffu, v, 1);
        v += __shfl_xor_sync(0xffffffffu, v, 2);
        v += __shfl_xor_sync(0xffffffffu, v, 4);
        v += __shfl_xor_sync(0xffffffffu, v, 8);
        if ((lane & 15) == 0) sl[16 * u + (tid >> 4)] = v;
    }
    __syncthreads();

#pragma unroll
    for (int mf = 0; mf < 2; mf++)
#pragma unroll
        for (int nf = 0; nf < 4; nf++) {
            int ql = warp_m + mf * 16 + gid;
            float li0 = 1.f / sl[ql];
            float li1 = 1.f / sl[ql + 8];
            int q = q0 + ql;
            int dcol = warp_n + nf * 8 + qid * 2;
            *(float2*)&g_ctx[((size_t)(b * Sc) + q) * DMc + h * Dc + dcol] =
                make_float2(acc[mf][nf][0] * li0, acc[mf][nf][1] * li0);
            *(float2*)&g_ctx[((size_t)(b * Sc) + q + 8) * DMc + h * Dc + dcol] =
                make_float2(acc[mf][nf][2] * li1, acc[mf][nf][3] * li1);
        }
}

// ---------------- fc GEMM: out = g_ctx @ W_fc ----------------
__global__ __launch_bounds__(256) void fc_mma(float* __restrict__ Cplain)
{
    extern __shared__ unsigned dyn[];
    const float* Ap = g_ctx;
    const float* Wt = g_Wt + 3 * DMc * DMc;

    int tid = threadIdx.x;
    int w = tid >> 5, lane = tid & 31, gid = lane >> 2, qid = lane & 3;
    int warp_m = (w >> 2) * 64, warp_n = (w & 3) * 32;
    int m0 = blockIdx.y * 128, n0 = blockIdx.x * 128;

    float2 ra[8], rb[8];
    float acc[4][4][4];
#pragma unroll
    for (int i = 0; i < 4; i++)
#pragma unroll
        for (int j = 0; j < 4; j++)
#pragma unroll
            for (int r = 0; r < 4; r++) acc[i][j][r] = 0.f;

#pragma unroll
    for (int u = 0; u < 8; u++) {
        int e = tid + 256 * u;
        int m = e >> 4, k2 = e & 15;
        ra[u] = *(const float2*)&Ap[(m0 + m) * 512 + 2 * k2];
        rb[u] = *(const float2*)&Wt[(n0 + m) * 512 + 2 * k2];
    }
#pragma unroll
    for (int u = 0; u < 8; u++) {
        int e = tid + 256 * u;
        int m = e >> 4, k2 = e & 15;
        *(uint2*)&dyn[m * 36 + 2 * k2] = make_uint2(f2tf(ra[u].x), f2tf(ra[u].y));
        *(uint2*)&dyn[128 * 36 + m * 36 + 2 * k2] = make_uint2(f2tf(rb[u].x), f2tf(rb[u].y));
    }
    __syncthreads();

    int buf = 0;
    for (int kt = 0; kt < 512; kt += 32) {
        bool more = (kt + 32) < 512;
        if (more) {
#pragma unroll
            for (int u = 0; u < 8; u++) {
                int e = tid + 256 * u;
                int m = e >> 4, k2 = e & 15;
                ra[u] = *(const float2*)&Ap[(m0 + m) * 512 + kt + 32 + 2 * k2];
                rb[u] = *(const float2*)&Wt[(n0 + m) * 512 + kt + 32 + 2 * k2];
            }
        }
        {
            unsigned* Asb = dyn + buf * 2 * 128 * 36;
            unsigned* Bsb = Asb + 128 * 36;
#pragma unroll
            for (int ks = 0; ks < 4; ks++) {
                unsigned a[4][4], b[4][2];
#pragma unroll
                for (int mf = 0; mf < 4; mf++) {
                    int r = warp_m + mf * 16 + gid;
                    a[mf][0] = Asb[r * 36 + ks * 8 + qid];
                    a[mf][1] = Asb[(r + 8) * 36 + ks * 8 + qid];
                    a[mf][2] = Asb[r * 36 + ks * 8 + qid + 4];
                    a[mf][3] = Asb[(r + 8) * 36 + ks * 8 + qid + 4];
                }
#pragma unroll
                for (int nf = 0; nf < 4; nf++) {
                    int r = warp_n + nf * 8 + gid;
                    b[nf][0] = Bsb[r * 36 + ks * 8 + qid];
                    b[nf][1] = Bsb[r * 36 + ks * 8 + qid + 4];
                }
#pragma unroll
                for (int mf = 0; mf < 4; mf++)
#pragma unroll
                    for (int nf = 0; nf < 4; nf++)
                        mma8(acc[mf][nf], a[mf], b[nf]);
            }
        }
        if (more) {
            unsigned* Asb = dyn + (buf ^ 1) * 2 * 128 * 36;
            unsigned* Bsb = Asb + 128 * 36;
#pragma unroll
            for (int u = 0; u < 8; u++) {
                int e = tid + 256 * u;
                int m = e >> 4, k2 = e & 15;
                *(uint2*)&Asb[m * 36 + 2 * k2] = make_uint2(f2tf(ra[u].x), f2tf(ra[u].y));
                *(uint2*)&Bsb[m * 36 + 2 * k2] = make_uint2(f2tf(rb[u].x), f2tf(rb[u].y));
            }
        }
        __syncthreads();
        buf ^= 1;
    }

#pragma unroll
    for (int mf = 0; mf < 4; mf++)
#pragma unroll
        for (int nf = 0; nf < 4; nf++) {
            int m = m0 + warp_m + mf * 16 + gid;
            int n = n0 + warp_n + nf * 8 + qid * 2;
            *(float2*)&Cplain[m * 512 + n] = make_float2(acc[mf][nf][0], acc[mf][nf][1]);
            *(float2*)&Cplain[(m + 8) * 512 + n] = make_float2(acc[mf][nf][2], acc[mf][nf][3]);
        }
}

// ---------------- launch ------------------------------------------------------
extern "C" void kernel_launch(void* const* d_in, const int* in_sizes, int n_in,
                              void* d_out, int out_size)
{
    (void)in_sizes; (void)n_in; (void)out_size;
    const float* inQ  = (const float*)d_in[0];
    const float* inK  = (const float*)d_in[1];
    const float* inV  = (const float*)d_in[2];
    const int*   mask = (const int*)d_in[3];
    const float* edge = (const float*)d_in[4];
    const float* WQ   = (const float*)d_in[5];
    const float* WK   = (const float*)d_in[6];
    const float* WV   = (const float*)d_in[7];
    const float* Wfc  = (const float*)d_in[8];

    float* out     = (float*)d_out;
    float* out_avg = out + Bc * Sc * DMc;

    const int GEMM_SMEM = 2 * 2 * 128 * 36 * 4;      // 73728
    const int SC_SMEM   = 2 * 128 * 68 * 4;          // 69632
    const int AV_SMEM   = 2 * (128 + 64) * 36 * 4;   // 55296
    cudaFuncSetAttribute(proj_plus,   cudaFuncAttributeMaxDynamicSharedMemorySize, GEMM_SMEM);
    cudaFuncSetAttribute(fc_mma,      cudaFuncAttributeMaxDynamicSharedMemorySize, GEMM_SMEM);
    cudaFuncSetAttribute(scores_plus, cudaFuncAttributeMaxDynamicSharedMemorySize, SC_SMEM);
    cudaFuncSetAttribute(av_plus,     cudaFuncAttributeMaxDynamicSharedMemorySize, AV_SMEM);

    transpose_w<<<dim3(16, 16, 4), dim3(32, 8)>>>(WQ, WK, WV, Wfc);

    proj_plus<<<dim3(4, 64, 4), 256, GEMM_SMEM>>>(inQ, inK, inV, mask, edge);

    scores_plus<<<dim3(8, 8, 128), 256, SC_SMEM>>>();

    av_plus<<<dim3(8, 64, 17), 256, AV_SMEM>>>(out_avg);

    fc_mma<<<dim3(4, 64), 256, GEMM_SMEM>>>(out);
}